// round 5
// baseline (speedup 1.0000x reference)
#include <cuda_runtime.h>
#include <cstdint>

#define BB   8
#define SRC  512
#define TGT  128
#define ED   512
#define DD   512

// Scratch (device globals: allocation-free per harness rules)
__device__ float g_mp[BB * SRC * DD];   // 8 MB: memory @ Wa_m
__device__ float g_dp[BB * TGT * DD];   // 2 MB: decoder_state @ Wa_d
__device__ float g_a [BB * TGT * SRC];  // 2 MB: softmax probabilities

__device__ __forceinline__ float fast_tanh(float x) {
    float y;
    asm("tanh.approx.f32 %0, %1;" : "=f"(y) : "f"(x));
    return y;
}

__device__ __forceinline__ void cp_async16(void* smem_dst, const void* gmem_src) {
    uint32_t d = (uint32_t)__cvta_generic_to_shared(smem_dst);
    asm volatile("cp.async.ca.shared.global [%0], [%1], 16;\n" :: "r"(d), "l"(gmem_src));
}
#define CP_COMMIT() asm volatile("cp.async.commit_group;\n")
#define CP_WAIT1()  asm volatile("cp.async.wait_group 1;\n")
#define CP_WAIT0()  asm volatile("cp.async.wait_group 0;\n")

// ---------------------------------------------------------------------------
// Projection GEMM: C[M,512] = A[M,512] @ W[512,512]
// BM=128, BN=64, BK=16, 256 threads, 8x4 micro-tile, double-buffered smem.
// ---------------------------------------------------------------------------
__global__ void __launch_bounds__(256) gemm_pre(
    const float* __restrict__ memory,
    const float* __restrict__ dec,
    const float* __restrict__ Wa)
{
    __shared__ float As[2][16][132];
    __shared__ float Bs[2][16][64];

    const int tid = threadIdx.x;
    const int bn  = blockIdx.x;
    const int by  = blockIdx.y;

    const float *A, *W;
    float *C;
    int bm;
    if (by < 32) { A = memory; W = Wa + 512 * 512; C = g_mp; bm = by; }
    else         { A = dec;    W = Wa;             C = g_dp; bm = by - 32; }

    const float* Ab = A + (size_t)bm * 128 * 512;
    const float* Wb = W + bn * 64;
    float*       Cb = C + (size_t)bm * 128 * 512 + bn * 64;

    const int arow = tid >> 1;
    const int acol = (tid & 1) * 8;
    const int brow = tid >> 4;
    const int bcol = (tid & 15) * 4;
    const int tr   = (tid >> 4) * 8;
    const int tc   = (tid & 15) * 4;

    float acc[8][4];
    #pragma unroll
    for (int i = 0; i < 8; i++)
        #pragma unroll
        for (int j = 0; j < 4; j++) acc[i][j] = 0.f;

    float4 a0 = *(const float4*)(Ab + (size_t)arow * 512 + acol);
    float4 a1 = *(const float4*)(Ab + (size_t)arow * 512 + acol + 4);
    float4 b0 = *(const float4*)(Wb + (size_t)brow * 512 + bcol);

    int p = 0;
    for (int it = 0; it < 32; it++) {
        As[p][acol + 0][arow] = a0.x;
        As[p][acol + 1][arow] = a0.y;
        As[p][acol + 2][arow] = a0.z;
        As[p][acol + 3][arow] = a0.w;
        As[p][acol + 4][arow] = a1.x;
        As[p][acol + 5][arow] = a1.y;
        As[p][acol + 6][arow] = a1.z;
        As[p][acol + 7][arow] = a1.w;
        *(float4*)(&Bs[p][brow][bcol]) = b0;
        __syncthreads();

        if (it < 31) {
            const int k0 = (it + 1) * 16;
            a0 = *(const float4*)(Ab + (size_t)arow * 512 + k0 + acol);
            a1 = *(const float4*)(Ab + (size_t)arow * 512 + k0 + acol + 4);
            b0 = *(const float4*)(Wb + (size_t)(k0 + brow) * 512 + bcol);
        }

        #pragma unroll
        for (int k = 0; k < 16; k++) {
            float rm[8], rn[4];
            *(float4*)(rm)     = *(const float4*)(&As[p][k][tr]);
            *(float4*)(rm + 4) = *(const float4*)(&As[p][k][tr + 4]);
            *(float4*)(rn)     = *(const float4*)(&Bs[p][k][tc]);
            #pragma unroll
            for (int i = 0; i < 8; i++)
                #pragma unroll
                for (int j = 0; j < 4; j++)
                    acc[i][j] = fmaf(rm[i], rn[j], acc[i][j]);
        }
        p ^= 1;
    }

    #pragma unroll
    for (int i = 0; i < 8; i++)
        *(float4*)(Cb + (size_t)(tr + i) * 512 + tc) = *(float4*)(acc[i]);
}

// ---------------------------------------------------------------------------
// Score + masked softmax -> g_a.   MUFU-bound: 268M tanh.
// Block = (b, 4 t-values). Tile = 128 s-rows x 32 k, pitch 36, DOUBLE-buffered
// via cp.async: chunk c (c = stage*16 + kci, stage 0..3 of 128 s each).
// Warp w: rows (w&3)*32+lane; t-pair tg = (w>>2)*2. Lane accumulates
// acc[stage*2 + tt] = e[t0+tg+tt, stage*128 + (w&3)*32 + lane].
// Smem: 2*18KB tile + 8KB dp + 2KB va + red = 47KB -> fits static limit.
// ---------------------------------------------------------------------------
#define TILEW (128 * 36)

__global__ void __launch_bounds__(256, 2) score_kernel(
    const float* __restrict__ Va,
    const int* __restrict__ mask)
{
    __shared__ float s_mp[2 * TILEW];   // 36 KB
    __shared__ float s_dp[4 * 512];     //  8 KB
    __shared__ float s_va[512];         //  2 KB
    __shared__ float s_red[32];

    const int b    = blockIdx.y;
    const int t0   = blockIdx.x * 4;
    const int tid  = threadIdx.x;
    const int lane = tid & 31;
    const int w    = tid >> 5;
    const int tg   = (w >> 2) * 2;        // t-pair base (0 or 2)
    const int myrow = (w & 3) * 32 + lane;

    // stage dp rows (t0..t0+3) and Va (plain loads; covered by first barrier)
    {
        const float4* dpg = (const float4*)(g_dp + (size_t)(b * TGT + t0) * 512);
        ((float4*)s_dp)[tid]       = dpg[tid];
        ((float4*)s_dp)[tid + 256] = dpg[tid + 256];
        if (tid < 128) ((float4*)s_va)[tid] = ((const float4*)Va)[tid];
    }

    const float* mp_b = g_mp + (size_t)b * SRC * 512;
    // loader mapping: 4 cp.async.16 per thread per chunk
    const int lrow[4] = { (tid + 0) >> 3, (tid + 256) >> 3, (tid + 512) >> 3, (tid + 768) >> 3 };
    const int lc4     = (tid & 7) << 2;

    // prologue: chunk 0 (stage 0, kc 0) -> buf 0
    {
        const float* src = mp_b;   // stage 0, kc 0
        float* dst = s_mp;
        #pragma unroll
        for (int i = 0; i < 4; i++)
            cp_async16(dst + lrow[i] * 36 + lc4, src + (size_t)lrow[i] * 512 + lc4);
        CP_COMMIT();
    }

    float acc[8];
    #pragma unroll
    for (int i = 0; i < 8; i++) acc[i] = 0.f;

    for (int c = 0; c < 64; c++) {
        // issue chunk c+1 into the other buffer
        if (c < 63) {
            const int cn    = c + 1;
            const int stg   = cn >> 4;
            const int kc    = (cn & 15) * 32;
            const float* src = mp_b + (size_t)(stg * 128) * 512 + kc;
            float* dst = s_mp + (cn & 1) * TILEW;
            #pragma unroll
            for (int i = 0; i < 4; i++)
                cp_async16(dst + lrow[i] * 36 + lc4, src + (size_t)lrow[i] * 512 + lc4);
            CP_COMMIT();
            CP_WAIT1();
        } else {
            CP_WAIT0();
        }
        __syncthreads();

        const int stage = c >> 4;
        const int kc    = (c & 15) * 32;
        const float* mrow_s = s_mp + (c & 1) * TILEW + myrow * 36;
        float* ep = acc + stage * 2;

        #pragma unroll
        for (int k = 0; k < 32; k += 4) {
            float4 m4 = *(const float4*)(mrow_s + k);
            float4 v4 = *(const float4*)(s_va + kc + k);
            #pragma unroll
            for (int tt = 0; tt < 2; tt++) {
                float4 d4 = *(const float4*)(s_dp + (tg + tt) * 512 + kc + k);
                float a0 = fast_tanh(d4.x + m4.x);
                float a1 = fast_tanh(d4.y + m4.y);
                float a2 = fast_tanh(d4.z + m4.z);
                float a3 = fast_tanh(d4.w + m4.w);
                ep[tt] = fmaf(v4.x, a0, ep[tt]);
                ep[tt] = fmaf(v4.y, a1, ep[tt]);
                ep[tt] = fmaf(v4.z, a2, ep[tt]);
                ep[tt] = fmaf(v4.w, a3, ep[tt]);
            }
        }
        __syncthreads();   // compute done before this buffer is refilled
    }

    // mask: this lane's 4 s positions
    const int* mk = mask + b * SRC;
    const float NEG_INF = __int_as_float(0xff800000);
    #pragma unroll
    for (int st = 0; st < 4; st++) {
        if (mk[st * 128 + myrow] == 0) { acc[st * 2] = NEG_INF; acc[st * 2 + 1] = NEG_INF; }
    }

    // per-t max: warp reduce then across the 4 warps sharing t (w&3)
    #pragma unroll
    for (int tt = 0; tt < 2; tt++) {
        float m = fmaxf(fmaxf(acc[tt], acc[2 + tt]), fmaxf(acc[4 + tt], acc[6 + tt]));
        #pragma unroll
        for (int o = 16; o; o >>= 1) m = fmaxf(m, __shfl_xor_sync(0xffffffffu, m, o));
        if (lane == 0) s_red[(tg + tt) * 4 + (w & 3)] = m;
    }
    __syncthreads();
    float mx[2], inv[2];
    #pragma unroll
    for (int tt = 0; tt < 2; tt++) {
        const float* r = s_red + (tg + tt) * 4;
        mx[tt] = fmaxf(fmaxf(r[0], r[1]), fmaxf(r[2], r[3]));
    }

    // per-t sum
    #pragma unroll
    for (int tt = 0; tt < 2; tt++) {
        float s = 0.f;
        #pragma unroll
        for (int st = 0; st < 4; st++) {
            float p = __expf(acc[st * 2 + tt] - mx[tt]);
            acc[st * 2 + tt] = p;
            s += p;
        }
        #pragma unroll
        for (int o = 16; o; o >>= 1) s += __shfl_xor_sync(0xffffffffu, s, o);
        if (lane == 0) s_red[16 + (tg + tt) * 4 + (w & 3)] = s;
    }
    __syncthreads();
    #pragma unroll
    for (int tt = 0; tt < 2; tt++) {
        const float* r = s_red + 16 + (tg + tt) * 4;
        inv[tt] = 1.f / (r[0] + r[1] + r[2] + r[3]);
    }

    #pragma unroll
    for (int tt = 0; tt < 2; tt++) {
        float* arow = g_a + (size_t)(b * TGT + t0 + tg + tt) * SRC;
        #pragma unroll
        for (int st = 0; st < 4; st++)
            arow[st * 128 + myrow] = acc[st * 2 + tt] * inv[tt];
    }
}

// ---------------------------------------------------------------------------
// Context GEMM: out[b] (128t x 512e) = g_a[b] (128 x 512s) @ memory[b] (512 x 512)
// ---------------------------------------------------------------------------
__global__ void __launch_bounds__(256) context_kernel(
    const float* __restrict__ memory,
    float* __restrict__ out)
{
    __shared__ float As[64 * 32];
    __shared__ float Bs[32 * 32];

    const int cb  = blockIdx.x;
    const int tb  = blockIdx.y;
    const int b   = blockIdx.z;
    const int tid = threadIdx.x;
    const int col = tid & 31;
    const int tr0 = (tid >> 5) * 8;

    const float* Ab = g_a + (size_t)(b * TGT + tb * 64) * SRC;
    const float* Bb = memory + (size_t)b * SRC * ED + cb * 32;

    const int ar = tid >> 2;
    const int ac = (tid & 3) * 8;
    const int br = tid >> 3;
    const int bc = (tid & 7) * 4;

    float acc[8];
    #pragma unroll
    for (int i = 0; i < 8; i++) acc[i] = 0.f;

    for (int sc = 0; sc < SRC; sc += 32) {
        __syncthreads();
        *(float4*)(As + ar * 32 + ac)     = *(const float4*)(Ab + (size_t)ar * SRC + sc + ac);
        *(float4*)(As + ar * 32 + ac + 4) = *(const float4*)(Ab + (size_t)ar * SRC + sc + ac + 4);
        *(float4*)(Bs + br * 32 + bc)     = *(const float4*)(Bb + (size_t)(sc + br) * ED + bc);
        __syncthreads();

        #pragma unroll
        for (int s = 0; s < 32; s++) {
            float bv = Bs[s * 32 + col];
            #pragma unroll
            for (int i = 0; i < 8; i++)
                acc[i] = fmaf(As[(tr0 + i) * 32 + s], bv, acc[i]);
        }
    }

    #pragma unroll
    for (int i = 0; i < 8; i++)
        out[(size_t)(b * TGT + tb * 64 + tr0 + i) * ED + cb * 32 + col] = acc[i];
}

// ---------------------------------------------------------------------------
extern "C" void kernel_launch(void* const* d_in, const int* in_sizes, int n_in,
                              void* d_out, int out_size)
{
    const float* memory = (const float*)d_in[0];
    const float* dec    = (const float*)d_in[1];
    const int*   mask   = (const int*)d_in[2];
    const float* Wa     = (const float*)d_in[3];
    const float* Va     = (const float*)d_in[4];
    float*       out    = (float*)d_out;

    (void)in_sizes; (void)n_in; (void)out_size;

    gemm_pre<<<dim3(8, 40), 256>>>(memory, dec, Wa);
    score_kernel<<<dim3(TGT / 4, BB), 256>>>(Va, mask);
    context_kernel<<<dim3(16, 2, BB), 256>>>(memory, out);
}

// round 7
// speedup vs baseline: 1.1694x; 1.1694x over previous
#include <cuda_runtime.h>
#include <cuda_bf16.h>
#include <cstdint>

#define BB   8
#define SRC  512
#define TGT  128
#define ED   512
#define DD   512
#define TT   4

// Scratch (device globals: allocation-free per harness rules)
__device__ float g_mp[BB * SRC * DD];          // 8 MB: memory @ Wa_m
__device__ float g_dp[BB * TGT * DD];          // 2 MB: decoder_state @ Wa_d
__device__ float g_a [BB * TGT * SRC];         // 2 MB: softmax probabilities
__device__ __nv_bfloat16 g_Ah[5120 * 512];     // A hi (memory rows 0..4095, dec 4096..5119)
__device__ __nv_bfloat16 g_Al[5120 * 512];     // A lo
__device__ __nv_bfloat16 g_Wth[2 * 512 * 512]; // W^T hi: sel 0 = Wa_d, 1 = Wa_m; [n][k]
__device__ __nv_bfloat16 g_Wtl[2 * 512 * 512]; // W^T lo

__device__ __forceinline__ float fast_tanh(float x) {
    float y;
    asm("tanh.approx.f32 %0, %1;" : "=f"(y) : "f"(x));
    return y;
}

__device__ __forceinline__ void cp_async16(void* smem_dst, const void* gmem_src) {
    uint32_t d = (uint32_t)__cvta_generic_to_shared(smem_dst);
    asm volatile("cp.async.ca.shared.global [%0], [%1], 16;\n" :: "r"(d), "l"(gmem_src));
}
#define CP_COMMIT() asm volatile("cp.async.commit_group;\n")
#define CP_WAIT1()  asm volatile("cp.async.wait_group 1;\n")
#define CP_WAIT0()  asm volatile("cp.async.wait_group 0;\n")

__device__ __forceinline__ void ldm_x4(uint32_t* r, uint32_t addr) {
    asm volatile("ldmatrix.sync.aligned.m8n8.x4.shared.b16 {%0,%1,%2,%3}, [%4];"
                 : "=r"(r[0]), "=r"(r[1]), "=r"(r[2]), "=r"(r[3]) : "r"(addr));
}
__device__ __forceinline__ void mma16816(float* c, const uint32_t* a, const uint32_t* b) {
    asm volatile("mma.sync.aligned.m16n8k16.row.col.f32.bf16.bf16.f32 "
                 "{%0,%1,%2,%3}, {%4,%5,%6,%7}, {%8,%9}, {%0,%1,%2,%3};"
                 : "+f"(c[0]), "+f"(c[1]), "+f"(c[2]), "+f"(c[3])
                 : "r"(a[0]), "r"(a[1]), "r"(a[2]), "r"(a[3]), "r"(b[0]), "r"(b[1]));
}

// ---------------------------------------------------------------------------
// Conversion: fp32 -> bf16 (hi, lo) for A = [memory ; dec]  (5120 x 512)
// ---------------------------------------------------------------------------
__global__ void __launch_bounds__(256) conv_a(
    const float* __restrict__ memory, const float* __restrict__ dec)
{
    const int idx = blockIdx.x * 256 + threadIdx.x;          // float4 index
    const float4 v = (idx < 524288) ? ((const float4*)memory)[idx]
                                    : ((const float4*)dec)[idx - 524288];
    float xs[4] = {v.x, v.y, v.z, v.w};
    __nv_bfloat16 h[4], l[4];
    #pragma unroll
    for (int i = 0; i < 4; i++) {
        h[i] = __float2bfloat16(xs[i]);
        l[i] = __float2bfloat16(xs[i] - __bfloat162float(h[i]));
    }
    ((__nv_bfloat162*)g_Ah)[idx * 2]     = __halves2bfloat162(h[0], h[1]);
    ((__nv_bfloat162*)g_Ah)[idx * 2 + 1] = __halves2bfloat162(h[2], h[3]);
    ((__nv_bfloat162*)g_Al)[idx * 2]     = __halves2bfloat162(l[0], l[1]);
    ((__nv_bfloat162*)g_Al)[idx * 2 + 1] = __halves2bfloat162(l[2], l[3]);
}

// ---------------------------------------------------------------------------
// Conversion: W^T hi/lo.  Wt[sel][n][k] = Wa[sel*512 + k][n];  sel 0=Wa_d, 1=Wa_m
// ---------------------------------------------------------------------------
__global__ void __launch_bounds__(256) conv_w(const float* __restrict__ Wa)
{
    __shared__ float s[32][33];
    const int tx = threadIdx.x, ty = threadIdx.y;            // 32 x 8
    const int bx = blockIdx.x, by = blockIdx.y, sel = blockIdx.z;

    #pragma unroll
    for (int j = 0; j < 32; j += 8)
        s[ty + j][tx] = Wa[(size_t)(sel * 512 + by * 32 + ty + j) * 512 + bx * 32 + tx];
    __syncthreads();

    #pragma unroll
    for (int j = 0; j < 32; j += 8) {
        const int n = bx * 32 + ty + j;
        const int k = by * 32 + tx;
        float x = s[tx][ty + j];
        __nv_bfloat16 h = __float2bfloat16(x);
        __nv_bfloat16 l = __float2bfloat16(x - __bfloat162float(h));
        const size_t o = (size_t)(sel * 512 + n) * 512 + k;
        g_Wth[o] = h;
        g_Wtl[o] = l;
    }
}

// ---------------------------------------------------------------------------
// Tensor-core projection GEMM via mma.sync (bf16 3-way split, fp32 accum).
// C[5120,512] = A @ W per-slab. Grid (8 n-tiles, 40 m-tiles), 256 thr, 8 warps.
// CTA tile 128x64; warp grid 4m x 2n -> warp tile 32x32 (2 m16 x 4 n8).
// K-chunks of 16, cp.async DOUBLE-buffered. smem rows pitch 48B:
// ldmatrix banks (12r+4c) mod 32 cover all 32 -> conflict-free.
// Per chunk/warp: 8 ldmatrix.x4 + 24 mma (3 splits: AhWh + AhWl + AlWh).
// ---------------------------------------------------------------------------
#define PITCH 48
#define OA_H  0
#define OA_L  6144
#define OW_H  12288
#define OW_L  15360
#define BUFSZ 18432

__global__ void __launch_bounds__(256, 2) gemm_tc()
{
    __shared__ char sm[2 * BUFSZ];                // 36 KB
    const uint32_t sb = (uint32_t)__cvta_generic_to_shared(sm);

    const int tid  = threadIdx.x;
    const int lane = tid & 31;
    const int w    = tid >> 5;
    const int wm   = w >> 1;                      // 0..3 (m)
    const int wn   = w & 1;                       // 0..1 (n)
    const int bn   = blockIdx.x;                  // 0..7
    const int by   = blockIdx.y;                  // 0..39

    const int m_base = by * 128;
    const int sel    = (by < 32) ? 1 : 0;
    float* C = (by < 32) ? (g_mp + (size_t)by * 128 * 512)
                         : (g_dp + (size_t)(by - 32) * 128 * 512);
    const __nv_bfloat16* Wh = g_Wth + (size_t)sel * 512 * 512 + (size_t)bn * 64 * 512;
    const __nv_bfloat16* Wl = g_Wtl + (size_t)sel * 512 * 512 + (size_t)bn * 64 * 512;

    // loader mapping: A: 128 rows x 2 chunks(16B) -> idx = tid (r=tid>>1, c=tid&1)
    //                 W: 64 rows x 2 chunks -> tid < 128
    const int ar = tid >> 1, ac = tid & 1;
    const int wr = (tid & 127) >> 1, wc = tid & 1;
    const bool do_w = (tid < 128);

    auto issue = [&](int kc, int buf) {
        char* B = sm + buf * BUFSZ;
        const size_t asrc = (size_t)(m_base + ar) * 512 + kc * 16 + ac * 8;
        cp_async16(B + OA_H + ar * PITCH + ac * 16, g_Ah + asrc);
        cp_async16(B + OA_L + ar * PITCH + ac * 16, g_Al + asrc);
        if (do_w) {
            const size_t wsrc = (size_t)wr * 512 + kc * 16 + wc * 8;
            cp_async16(B + OW_H + wr * PITCH + wc * 16, Wh + wsrc);
            cp_async16(B + OW_L + wr * PITCH + wc * 16, Wl + wsrc);
        }
        CP_COMMIT();
    };

    // ldmatrix address offsets (within a buffer)
    const uint32_t a_off = (uint32_t)((wm * 32 + (lane & 15)) * PITCH + (lane >> 4) * 16);
    const uint32_t b_off = (uint32_t)((wn * 32 + (lane & 7) + ((lane >> 4) * 8)) * PITCH
                                      + (((lane >> 3) & 1) * 16));

    float acc[2][4][4];
    #pragma unroll
    for (int i = 0; i < 2; i++)
        #pragma unroll
        for (int j = 0; j < 4; j++)
            #pragma unroll
            for (int e = 0; e < 4; e++) acc[i][j][e] = 0.f;

    issue(0, 0);

    for (int kc = 0; kc < 32; kc++) {
        if (kc < 31) { issue(kc + 1, (kc + 1) & 1); CP_WAIT1(); }
        else         { CP_WAIT0(); }
        __syncthreads();

        const uint32_t base = sb + (kc & 1) * BUFSZ;
        uint32_t ah[2][4], al[2][4], bh[2][4], bl[2][4];
        #pragma unroll
        for (int i = 0; i < 2; i++) {
            ldm_x4(ah[i], base + OA_H + a_off + i * 16 * PITCH);
            ldm_x4(al[i], base + OA_L + a_off + i * 16 * PITCH);
        }
        #pragma unroll
        for (int j = 0; j < 2; j++) {
            ldm_x4(bh[j], base + OW_H + b_off + j * 16 * PITCH);
            ldm_x4(bl[j], base + OW_L + b_off + j * 16 * PITCH);
        }

        #pragma unroll
        for (int i = 0; i < 2; i++)
            #pragma unroll
            for (int j = 0; j < 4; j++) {
                const uint32_t* ph = &bh[j >> 1][2 * (j & 1)];
                const uint32_t* pl = &bl[j >> 1][2 * (j & 1)];
                mma16816(acc[i][j], ah[i], ph);
                mma16816(acc[i][j], ah[i], pl);
                mma16816(acc[i][j], al[i], ph);
            }
        __syncthreads();
    }

    // epilogue: C[m][n], fragment rows lane>>2 (+8), cols (lane&3)*2 (+1)
    #pragma unroll
    for (int i = 0; i < 2; i++) {
        const int r0 = wm * 32 + i * 16 + (lane >> 2);
        #pragma unroll
        for (int j = 0; j < 4; j++) {
            const int c0 = bn * 64 + wn * 32 + j * 8 + (lane & 3) * 2;
            *(float2*)(C + (size_t)r0 * 512 + c0)       = make_float2(acc[i][j][0], acc[i][j][1]);
            *(float2*)(C + (size_t)(r0 + 8) * 512 + c0) = make_float2(acc[i][j][2], acc[i][j][3]);
        }
    }
}

// ---------------------------------------------------------------------------
// Score + masked softmax -> g_a.   MUFU-bound: tanh.approx rt=16 (measured).
// R4 version (best measured): 8 warps, 4 t/block, 256-row tile pitch 36.
// ---------------------------------------------------------------------------
__global__ void __launch_bounds__(256, 4) score_kernel(
    const float* __restrict__ Va,
    const int* __restrict__ mask)
{
    __shared__ float s_mp[256 * 36];
    __shared__ float s_dp[TT * 512];
    __shared__ float s_va[512];
    __shared__ float s_red[TT * 8];

    const int b    = blockIdx.y;
    const int t0   = blockIdx.x * TT;
    const int tid  = threadIdx.x;
    const int lane = tid & 31;
    const int w    = tid >> 5;

    {
        const float4* dpg = (const float4*)(g_dp + (size_t)(b * TGT + t0) * 512);
        ((float4*)s_dp)[tid]       = dpg[tid];
        ((float4*)s_dp)[tid + 256] = dpg[tid + 256];
        if (tid < 128) ((float4*)s_va)[tid] = ((const float4*)Va)[tid];
    }

    float acc[2 * TT];
    #pragma unroll
    for (int i = 0; i < 2 * TT; i++) acc[i] = 0.f;

    const int r0    = tid >> 3;
    const int c4    = (tid & 7) << 2;
    const int myrow = w * 32 + lane;

    #pragma unroll
    for (int stage = 0; stage < 2; stage++) {
        const float* mpg = g_mp + (size_t)(b * SRC + stage * 256) * 512;
        float* ep = acc + stage * TT;
        for (int kc = 0; kc < 512; kc += 32) {
            __syncthreads();
            #pragma unroll
            for (int rr = 0; rr < 256; rr += 32) {
                float4 v = *(const float4*)(mpg + (size_t)(r0 + rr) * 512 + kc + c4);
                *(float4*)(s_mp + (r0 + rr) * 36 + c4) = v;
            }
            __syncthreads();

            const float* mrow_s = s_mp + myrow * 36;
            #pragma unroll
            for (int k = 0; k < 32; k += 4) {
                float4 m4 = *(const float4*)(mrow_s + k);
                float4 v4 = *(const float4*)(s_va + kc + k);
                #pragma unroll
                for (int t = 0; t < TT; t++) {
                    float4 d4 = *(const float4*)(s_dp + t * 512 + kc + k);
                    float a0 = fast_tanh(d4.x + m4.x);
                    float a1 = fast_tanh(d4.y + m4.y);
                    float a2 = fast_tanh(d4.z + m4.z);
                    float a3 = fast_tanh(d4.w + m4.w);
                    ep[t] = fmaf(v4.x, a0, ep[t]);
                    ep[t] = fmaf(v4.y, a1, ep[t]);
                    ep[t] = fmaf(v4.z, a2, ep[t]);
                    ep[t] = fmaf(v4.w, a3, ep[t]);
                }
            }
        }
    }

    const int* mk = mask + b * SRC;
    const int s0 = myrow, s1 = 256 + myrow;
    const float NEG_INF = __int_as_float(0xff800000);
    const bool m0 = (mk[s0] != 0), m1 = (mk[s1] != 0);
    #pragma unroll
    for (int t = 0; t < TT; t++) {
        if (!m0) acc[t]      = NEG_INF;
        if (!m1) acc[TT + t] = NEG_INF;
    }

    float mx[TT];
    #pragma unroll
    for (int t = 0; t < TT; t++) {
        float m = fmaxf(acc[t], acc[TT + t]);
        #pragma unroll
        for (int o = 16; o; o >>= 1) m = fmaxf(m, __shfl_xor_sync(0xffffffffu, m, o));
        if (lane == 0) s_red[t * 8 + w] = m;
    }
    __syncthreads();
    #pragma unroll
    for (int t = 0; t < TT; t++) {
        float m = s_red[t * 8 + 0];
        #pragma unroll
        for (int i = 1; i < 8; i++) m = fmaxf(m, s_red[t * 8 + i]);
        mx[t] = m;
    }
    __syncthreads();

    float inv[TT];
    #pragma unroll
    for (int t = 0; t < TT; t++) {
        float p0 = __expf(acc[t]      - mx[t]);
        float p1 = __expf(acc[TT + t] - mx[t]);
        acc[t] = p0; acc[TT + t] = p1;
        float s = p0 + p1;
        #pragma unroll
        for (int o = 16; o; o >>= 1) s += __shfl_xor_sync(0xffffffffu, s, o);
        if (lane == 0) s_red[t * 8 + w] = s;
    }
    __syncthreads();
    #pragma unroll
    for (int t = 0; t < TT; t++) {
        float s = s_red[t * 8 + 0];
        #pragma unroll
        for (int i = 1; i < 8; i++) s += s_red[t * 8 + i];
        inv[t] = 1.f / s;
    }

    #pragma unroll
    for (int t = 0; t < TT; t++) {
        float* arow = g_a + (size_t)(b * TGT + t0 + t) * SRC;
        arow[s0] = acc[t]      * inv[t];
        arow[s1] = acc[TT + t] * inv[t];
    }
}

// ---------------------------------------------------------------------------
// Context GEMM: out[b] = g_a[b] (128 x 512) @ memory[b] (512 x 512)
// ---------------------------------------------------------------------------
__global__ void __launch_bounds__(256) context_kernel(
    const float* __restrict__ memory,
    float* __restrict__ out)
{
    __shared__ float As[64 * 32];
    __shared__ float Bs[32 * 32];

    const int cb  = blockIdx.x;
    const int tb  = blockIdx.y;
    const int b   = blockIdx.z;
    const int tid = threadIdx.x;
    const int col = tid & 31;
    const int tr0 = (tid >> 5) * 8;

    const float* Ab = g_a + (size_t)(b * TGT + tb * 64) * SRC;
    const float* Bb = memory + (size_t)b * SRC * ED + cb * 32;

    const int ar = tid >> 2;
    const int ac = (tid & 3) * 8;
    const int br = tid >> 3;
    const int bc = (tid & 7) * 4;

    float acc[8];
    #pragma unroll
    for (int i = 0; i < 8; i++) acc[i] = 0.f;

    for (int sc = 0; sc < SRC; sc += 32) {
        __syncthreads();
        *(float4*)(As + ar * 32 + ac)     = *(const float4*)(Ab + (size_t)ar * SRC + sc + ac);
        *(float4*)(As + ar * 32 + ac + 4) = *(const float4*)(Ab + (size_t)ar * SRC + sc + ac + 4);
        *(float4*)(Bs + br * 32 + bc)     = *(const float4*)(Bb + (size_t)(sc + br) * ED + bc);
        __syncthreads();

        #pragma unroll
        for (int s = 0; s < 32; s++) {
            float bv = Bs[s * 32 + col];
            #pragma unroll
            for (int i = 0; i < 8; i++)
                acc[i] = fmaf(As[(tr0 + i) * 32 + s], bv, acc[i]);
        }
    }

    #pragma unroll
    for (int i = 0; i < 8; i++)
        out[(size_t)(b * TGT + tb * 64 + tr0 + i) * ED + cb * 32 + col] = acc[i];
}

// ---------------------------------------------------------------------------
extern "C" void kernel_launch(void* const* d_in, const int* in_sizes, int n_in,
                              void* d_out, int out_size)
{
    const float* memory = (const float*)d_in[0];
    const float* dec    = (const float*)d_in[1];
    const int*   mask   = (const int*)d_in[2];
    const float* Wa     = (const float*)d_in[3];
    const float* Va     = (const float*)d_in[4];
    float*       out    = (float*)d_out;

    (void)in_sizes; (void)n_in; (void)out_size;

    conv_a<<<2560, 256>>>(memory, dec);
    conv_w<<<dim3(16, 16, 2), dim3(32, 8)>>>(Wa);
    gemm_tc<<<dim3(8, 40), 256>>>();
    score_kernel<<<dim3(TGT / TT, BB), 256>>>(Va, mask);
    context_kernel<<<dim3(16, 2, BB), 256>>>(memory, out);
}